// round 2
// baseline (speedup 1.0000x reference)
#include <cuda_runtime.h>

#define NN 200000
#define EE 640000
#define SB 512
#define NBLK 391   // ceil(NN / SB)

// ---------------- persistent device scratch (no allocations allowed) ----------------
__device__ float g_hA[(size_t)NN * 128];
__device__ float g_hB[(size_t)NN * 128];
__device__ float g_dis[NN];
__device__ int   g_cnt[NN];
__device__ int   g_fill[NN];
__device__ int   g_row[NN + 1];
__device__ int   g_col[EE];
__device__ float g_en[EE];
__device__ int   g_part[SB];
__device__ int   g_is64;

// ---------------- edge dtype probe (int64 vs int32) ----------------
__global__ void k_detect(const void* ei) {
    const long long* p = (const long long*)ei;
    int ok = 1;
    #pragma unroll
    for (int i = 0; i < 4; i++) {
        long long v = p[i];
        if (v < 0 || v >= NN) ok = 0;
    }
    g_is64 = ok;
}

__device__ __forceinline__ int edge_at(const void* ei, int idx) {
    int v;
    if (g_is64) v = (int)((const long long*)ei)[idx];
    else        v = ((const int*)ei)[idx];
    // clamp: a wrong dtype guess must produce wrong numbers, not a crash
    return min(max(v, 0), NN - 1);
}

// ---------------- CSR build ----------------
__global__ void k_zero() {
    int i = blockIdx.x * blockDim.x + threadIdx.x;
    if (i < NN) { g_cnt[i] = 0; g_fill[i] = 0; }
}

__global__ void k_count(const void* __restrict__ ei) {
    int e = blockIdx.x * blockDim.x + threadIdx.x;
    if (e < EE) atomicAdd(&g_cnt[edge_at(ei, EE + e)], 1);
}

__global__ void k_scanA() {
    __shared__ int tmp[SB];
    int tid = threadIdx.x;
    int i = blockIdx.x * SB + tid;
    int v = (i < NN) ? g_cnt[i] : 0;
    tmp[tid] = v; __syncthreads();
    for (int off = 1; off < SB; off <<= 1) {
        int t = (tid >= off) ? tmp[tid - off] : 0;
        __syncthreads();
        if (tid >= off) tmp[tid] += t;
        __syncthreads();
    }
    if (i < NN) g_row[i + 1] = tmp[tid];
    if (tid == SB - 1) g_part[blockIdx.x] = tmp[tid];
}

__global__ void k_scanB() {
    __shared__ int tmp[SB];
    int tid = threadIdx.x;
    int v = (tid < NBLK) ? g_part[tid] : 0;
    tmp[tid] = v; __syncthreads();
    for (int off = 1; off < SB; off <<= 1) {
        int t = (tid >= off) ? tmp[tid - off] : 0;
        __syncthreads();
        if (tid >= off) tmp[tid] += t;
        __syncthreads();
    }
    if (tid < NBLK) g_part[tid] = tmp[tid] - v;   // exclusive block offsets
}

__global__ void k_scanC() {
    int i = blockIdx.x * blockDim.x + threadIdx.x;
    if (i < NN) {
        g_row[i + 1] += g_part[i / SB];
        if (i == 0) g_row[0] = 0;
    }
}

__global__ void k_dis() {
    int i = blockIdx.x * blockDim.x + threadIdx.x;
    if (i < NN) g_dis[i] = rsqrtf((float)g_cnt[i] + 1.0f);
}

__global__ void k_fill(const void* __restrict__ ei) {
    int e = blockIdx.x * blockDim.x + threadIdx.x;
    if (e < EE) {
        int d = edge_at(ei, EE + e);
        int s = edge_at(ei, e);
        int p = g_row[d] + atomicAdd(&g_fill[d], 1);
        g_col[p] = s;
        g_en[p] = g_dis[s] * g_dis[d];
    }
}

// ---------------- layer 1: aggregate x (2 feats) then [N,2]@[2,32]+b1, relu -> g_hB ----------------
__global__ void k_layer1(const float* __restrict__ x,
                         const float* __restrict__ W1,
                         const float* __restrict__ b1) {
    __shared__ float w[64], bb[32];
    if (threadIdx.x < 64) w[threadIdx.x] = W1[threadIdx.x];
    if (threadIdx.x < 32) bb[threadIdx.x] = b1[threadIdx.x];
    __syncthreads();
    int v = blockIdx.x * blockDim.x + threadIdx.x;
    if (v >= NN) return;
    float dv = g_dis[v];
    float a0 = dv * dv * x[2 * v];
    float a1 = dv * dv * x[2 * v + 1];
    int e0 = g_row[v], e1 = g_row[v + 1];
    for (int e = e0; e < e1; e++) {
        int s = g_col[e];
        float nm = g_en[e];
        a0 += nm * x[2 * s];
        a1 += nm * x[2 * s + 1];
    }
    float* out = &g_hB[(size_t)v * 32];
    #pragma unroll
    for (int c = 0; c < 32; c++) {
        float r = a0 * w[c] + a1 * w[32 + c] + bb[c];
        out[c] = fmaxf(r, 0.0f);
    }
}

// ---------------- fused layer: aggregate FIN feats into smem, then [64,FIN]@[FIN,128]+b, relu ----------------
// Block: 256 threads, 64 nodes/block (3125 blocks exactly covers 200000).
template <int FIN, bool IN_A>
__global__ void __launch_bounds__(256, 2) k_fused(const float* __restrict__ W,
                                                  const float* __restrict__ b) {
    constexpr int VEC = FIN / 32;
    extern __shared__ float smem[];
    float* Ws   = smem;                 // [FIN][128]
    float* aggT = smem + FIN * 128;     // [FIN][65] (pad 65 -> conflict-free)

    const float* hin  = IN_A ? g_hA : g_hB;
    float*       hout = IN_A ? g_hB : g_hA;

    // load W into shared (float4, coalesced)
    {
        const float4* Wg = (const float4*)W;
        float4* Wsv = (float4*)Ws;
        for (int idx = threadIdx.x; idx < FIN * 32; idx += 256) Wsv[idx] = Wg[idx];
    }

    // phase 1: aggregate 64 node rows into aggT (transposed)
    {
        int wid  = threadIdx.x >> 5;
        int lane = threadIdx.x & 31;
        #pragma unroll 1
        for (int n = 0; n < 8; n++) {
            int vloc = wid * 8 + n;
            int v = blockIdx.x * 64 + vloc;
            float dv = g_dis[v];
            float sn = dv * dv;
            float acc[VEC];
            const float* hr = hin + (size_t)v * FIN;
            #pragma unroll
            for (int j = 0; j < VEC; j++) acc[j] = sn * hr[lane + 32 * j];
            int e0 = g_row[v], e1 = g_row[v + 1];
            for (int e = e0; e < e1; e++) {
                int s = g_col[e];
                float nm = g_en[e];
                const float* hs = hin + (size_t)s * FIN;
                #pragma unroll
                for (int j = 0; j < VEC; j++) acc[j] += nm * hs[lane + 32 * j];
            }
            #pragma unroll
            for (int j = 0; j < VEC; j++) aggT[(lane + 32 * j) * 65 + vloc] = acc[j];
        }
    }
    __syncthreads();

    // phase 2: GEMM 64x128, thread tile 4 rows (stride 16) x 8 cols
    {
        int tx = threadIdx.x & 15;   // col group
        int ty = threadIdx.x >> 4;   // row group
        float acc[4][8];
        #pragma unroll
        for (int i = 0; i < 4; i++)
            #pragma unroll
            for (int j = 0; j < 8; j++) acc[i][j] = 0.0f;

        #pragma unroll 4
        for (int kk = 0; kk < FIN; kk++) {
            float a0 = aggT[kk * 65 + ty];
            float a1 = aggT[kk * 65 + ty + 16];
            float a2 = aggT[kk * 65 + ty + 32];
            float a3 = aggT[kk * 65 + ty + 48];
            float4 b0 = *(float4*)&Ws[kk * 128 + tx * 8];
            float4 b1 = *(float4*)&Ws[kk * 128 + tx * 8 + 4];
            float bv[8] = {b0.x, b0.y, b0.z, b0.w, b1.x, b1.y, b1.z, b1.w};
            float av[4] = {a0, a1, a2, a3};
            #pragma unroll
            for (int i = 0; i < 4; i++)
                #pragma unroll
                for (int j = 0; j < 8; j++) acc[i][j] += av[i] * bv[j];
        }

        int colb = tx * 8;
        float bias[8];
        #pragma unroll
        for (int j = 0; j < 8; j++) bias[j] = __ldg(&b[colb + j]);

        #pragma unroll
        for (int i = 0; i < 4; i++) {
            int row = blockIdx.x * 64 + ty + 16 * i;
            float4 o0, o1;
            o0.x = fmaxf(acc[i][0] + bias[0], 0.0f);
            o0.y = fmaxf(acc[i][1] + bias[1], 0.0f);
            o0.z = fmaxf(acc[i][2] + bias[2], 0.0f);
            o0.w = fmaxf(acc[i][3] + bias[3], 0.0f);
            o1.x = fmaxf(acc[i][4] + bias[4], 0.0f);
            o1.y = fmaxf(acc[i][5] + bias[5], 0.0f);
            o1.z = fmaxf(acc[i][6] + bias[6], 0.0f);
            o1.w = fmaxf(acc[i][7] + bias[7], 0.0f);
            *(float4*)&hout[(size_t)row * 128 + colb]     = o0;
            *(float4*)&hout[(size_t)row * 128 + colb + 4] = o1;
        }
    }
}

// ---------------- final: out = leakyrelu(h5 @ Wl + bl), one warp per node ----------------
__global__ void k_final(const float* __restrict__ Wl,
                        const float* __restrict__ bl,
                        float* __restrict__ out) {
    int warp = (blockIdx.x * blockDim.x + threadIdx.x) >> 5;   // exactly NN warps
    int lane = threadIdx.x & 31;
    float4 hv = *(const float4*)&g_hB[(size_t)warp * 128 + lane * 4];
    float4 w  = __ldg((const float4*)&Wl[lane * 4]);
    float s = hv.x * w.x + hv.y * w.y + hv.z * w.z + hv.w * w.w;
    #pragma unroll
    for (int off = 16; off; off >>= 1) s += __shfl_down_sync(0xFFFFFFFFu, s, off);
    if (lane == 0) {
        s += __ldg(bl);
        out[warp] = (s > 0.0f) ? s : 0.01f * s;
    }
}

// ---------------- launch ----------------
extern "C" void kernel_launch(void* const* d_in, const int* in_sizes, int n_in,
                              void* d_out, int out_size) {
    // Map inputs by order, with a fallback remap if the harness orders them
    // alphabetically (detected via the size signature).
    int ix = 0, ie = 1, iW1 = 2, ib1 = 3, iW2 = 4, ib2 = 5, iW3 = 6, ib3 = 7,
        iW4 = 8, ib4 = 9, iW5 = 10, ib5 = 11, iWl = 12, ibl = 13;
    if (n_in >= 14 && in_sizes[0] != 2 * NN) {
        if (in_sizes[0] == 64 && in_sizes[1] == 4096) {
            // alphabetical: W1 W2 W3 W4 W5 Wl b1 b2 b3 b4 b5 bl edge_index x
            iW1 = 0; iW2 = 1; iW3 = 2; iW4 = 3; iW5 = 4; iWl = 5;
            ib1 = 6; ib2 = 7; ib3 = 8; ib4 = 9; ib5 = 10; ibl = 11;
            ie = 12; ix = 13;
        }
    }

    const float* x  = (const float*)d_in[ix];
    const void*  ei = d_in[ie];
    const float* W1 = (const float*)d_in[iW1];
    const float* b1 = (const float*)d_in[ib1];
    const float* W2 = (const float*)d_in[iW2];
    const float* b2 = (const float*)d_in[ib2];
    const float* W3 = (const float*)d_in[iW3];
    const float* b3 = (const float*)d_in[ib3];
    const float* W4 = (const float*)d_in[iW4];
    const float* b4 = (const float*)d_in[ib4];
    const float* W5 = (const float*)d_in[iW5];
    const float* b5 = (const float*)d_in[ib5];
    const float* Wl = (const float*)d_in[iWl];
    const float* bl = (const float*)d_in[ibl];
    float* out = (float*)d_out;

    const int sh32  = (32 * 128 + 32 * 65) * 4;    // 24,704 B
    const int sh128 = (128 * 128 + 128 * 65) * 4;  // 98,816 B
    cudaFuncSetAttribute(k_fused<32,  false>, cudaFuncAttributeMaxDynamicSharedMemorySize, sh32);
    cudaFuncSetAttribute(k_fused<128, true >, cudaFuncAttributeMaxDynamicSharedMemorySize, sh128);
    cudaFuncSetAttribute(k_fused<128, false>, cudaFuncAttributeMaxDynamicSharedMemorySize, sh128);

    // dtype probe + CSR + norms
    k_detect<<<1, 1>>>(ei);
    k_zero <<<(NN + 255) / 256, 256>>>();
    k_count<<<(EE + 255) / 256, 256>>>(ei);
    k_scanA<<<NBLK, SB>>>();
    k_scanB<<<1, SB>>>();
    k_scanC<<<(NN + 255) / 256, 256>>>();
    k_dis  <<<(NN + 255) / 256, 256>>>();
    k_fill <<<(EE + 255) / 256, 256>>>(ei);

    // layers (aggregate-then-GEMM reordering)
    k_layer1<<<(NN + 255) / 256, 256>>>(x, W1, b1);           // -> g_hB [N,32]
    k_fused<32,  false><<<3125, 256, sh32 >>>(W2, b2);        // hB -> hA [N,128]
    k_fused<128, true ><<<3125, 256, sh128>>>(W3, b3);        // hA -> hB
    k_fused<128, false><<<3125, 256, sh128>>>(W4, b4);        // hB -> hA
    k_fused<128, true ><<<3125, 256, sh128>>>(W5, b5);        // hA -> hB

    k_final<<<NN / 8, 256>>>(Wl, bl, out);                     // 8 warps/block, exact
}

// round 3
// speedup vs baseline: 1.4923x; 1.4923x over previous
#include <cuda_runtime.h>
#include <cstdint>

#define NN 200000
#define EE 640000
#define SB 512
#define NBLK 391   // ceil(NN / SB)

// ---------------- persistent device scratch (no allocations allowed) ----------------
__device__ float g_hA[(size_t)NN * 128];
__device__ float g_hB[(size_t)NN * 128];
__device__ float g_dis[NN];
__device__ int   g_cnt[NN];
__device__ int   g_fill[NN];
__device__ int   g_row[NN + 1];
__device__ int   g_col[EE];
__device__ float g_en[EE];
__device__ int   g_part[SB];
__device__ int   g_is64;

// ---------------- helpers ----------------
__device__ __forceinline__ uint32_t f2tf32(float f) {
    uint32_t u;
    asm("cvt.rna.tf32.f32 %0, %1;" : "=r"(u) : "f"(f));
    return u;
}

__device__ __forceinline__ void mma_tf32(float c[4],
                                         uint32_t a0, uint32_t a1, uint32_t a2, uint32_t a3,
                                         uint32_t b0, uint32_t b1) {
    asm volatile(
        "mma.sync.aligned.m16n8k8.row.col.f32.tf32.tf32.f32 "
        "{%0,%1,%2,%3}, {%4,%5,%6,%7}, {%8,%9}, {%0,%1,%2,%3};\n"
        : "+f"(c[0]), "+f"(c[1]), "+f"(c[2]), "+f"(c[3])
        : "r"(a0), "r"(a1), "r"(a2), "r"(a3), "r"(b0), "r"(b1));
}

// ---------------- edge dtype probe (int64 vs int32) ----------------
__global__ void k_detect(const void* ei) {
    const long long* p = (const long long*)ei;
    int ok = 1;
    #pragma unroll
    for (int i = 0; i < 4; i++) {
        long long v = p[i];
        if (v < 0 || v >= NN) ok = 0;
    }
    g_is64 = ok;
}

__device__ __forceinline__ int edge_at(const void* ei, int idx) {
    int v;
    if (g_is64) v = (int)((const long long*)ei)[idx];
    else        v = ((const int*)ei)[idx];
    return min(max(v, 0), NN - 1);
}

// ---------------- CSR build ----------------
__global__ void k_zero() {
    int i = blockIdx.x * blockDim.x + threadIdx.x;
    if (i < NN) { g_cnt[i] = 0; g_fill[i] = 0; }
}

__global__ void k_count(const void* __restrict__ ei) {
    int e = blockIdx.x * blockDim.x + threadIdx.x;
    if (e < EE) atomicAdd(&g_cnt[edge_at(ei, EE + e)], 1);
}

__global__ void k_scanA() {
    __shared__ int tmp[SB];
    int tid = threadIdx.x;
    int i = blockIdx.x * SB + tid;
    int v = (i < NN) ? g_cnt[i] : 0;
    tmp[tid] = v; __syncthreads();
    for (int off = 1; off < SB; off <<= 1) {
        int t = (tid >= off) ? tmp[tid - off] : 0;
        __syncthreads();
        if (tid >= off) tmp[tid] += t;
        __syncthreads();
    }
    if (i < NN) g_row[i + 1] = tmp[tid];
    if (tid == SB - 1) g_part[blockIdx.x] = tmp[tid];
}

__global__ void k_scanB() {
    __shared__ int tmp[SB];
    int tid = threadIdx.x;
    int v = (tid < NBLK) ? g_part[tid] : 0;
    tmp[tid] = v; __syncthreads();
    for (int off = 1; off < SB; off <<= 1) {
        int t = (tid >= off) ? tmp[tid - off] : 0;
        __syncthreads();
        if (tid >= off) tmp[tid] += t;
        __syncthreads();
    }
    if (tid < NBLK) g_part[tid] = tmp[tid] - v;   // exclusive block offsets
}

__global__ void k_scanC() {
    int i = blockIdx.x * blockDim.x + threadIdx.x;
    if (i < NN) {
        g_row[i + 1] += g_part[i / SB];
        if (i == 0) g_row[0] = 0;
    }
}

__global__ void k_dis() {
    int i = blockIdx.x * blockDim.x + threadIdx.x;
    if (i < NN) g_dis[i] = rsqrtf((float)g_cnt[i] + 1.0f);
}

__global__ void k_fill(const void* __restrict__ ei) {
    int e = blockIdx.x * blockDim.x + threadIdx.x;
    if (e < EE) {
        int d = edge_at(ei, EE + e);
        int s = edge_at(ei, e);
        int p = g_row[d] + atomicAdd(&g_fill[d], 1);
        g_col[p] = s;
        g_en[p] = g_dis[s] * g_dis[d];
    }
}

// ---------------- layer 1: aggregate x (2 feats) then [N,2]@[2,32]+b1, relu -> g_hB ----------------
__global__ void k_layer1(const float* __restrict__ x,
                         const float* __restrict__ W1,
                         const float* __restrict__ b1) {
    __shared__ float w[64], bb[32];
    if (threadIdx.x < 64) w[threadIdx.x] = W1[threadIdx.x];
    if (threadIdx.x < 32) bb[threadIdx.x] = b1[threadIdx.x];
    __syncthreads();
    int v = blockIdx.x * blockDim.x + threadIdx.x;
    if (v >= NN) return;
    float dv = g_dis[v];
    float a0 = dv * dv * x[2 * v];
    float a1 = dv * dv * x[2 * v + 1];
    int e0 = g_row[v], e1 = g_row[v + 1];
    for (int e = e0; e < e1; e++) {
        int s = g_col[e];
        float nm = g_en[e];
        a0 += nm * x[2 * s];
        a1 += nm * x[2 * s + 1];
    }
    float* out = &g_hB[(size_t)v * 32];
    #pragma unroll
    for (int c = 0; c < 32; c++) {
        float r = a0 * w[c] + a1 * w[32 + c] + bb[c];
        out[c] = fmaxf(r, 0.0f);
    }
}

// ---------------- fused layer: aggregate FIN feats -> smem (tf32), then tf32 MMA [64,FIN]@[FIN,128] ----------------
// Block: 256 threads, 64 nodes/block (3125 blocks). Ws stride 136 (bank 8k+n distinct),
// aggS stride FIN+4 (bank 4r+k distinct) -> conflict-free fragment loads.
template <int FIN, bool IN_A>
__global__ void __launch_bounds__(256, 2) k_fused(const float* __restrict__ W,
                                                  const float* __restrict__ b) {
    constexpr int WS = 136;        // smem stride for W rows (128 data + 8 pad)
    constexpr int AS = FIN + 4;    // smem stride for agg rows
    extern __shared__ float smem[];
    float* Ws   = smem;            // [FIN][WS], tf32 bit patterns
    float* aggS = smem + FIN * WS; // [64][AS],  tf32 bit patterns

    const float* hin  = IN_A ? g_hA : g_hB;
    float*       hout = IN_A ? g_hB : g_hA;

    const int tid  = threadIdx.x;
    const int wid  = tid >> 5;
    const int lane = tid & 31;

    // ---- load W into shared, converting to tf32 (float4 in, uint4 out) ----
    for (int idx4 = tid; idx4 < FIN * 32; idx4 += 256) {
        int k  = idx4 >> 5;
        int n4 = idx4 & 31;
        float4 wv = ((const float4*)W)[idx4];
        uint4 t;
        t.x = f2tf32(wv.x); t.y = f2tf32(wv.y);
        t.z = f2tf32(wv.z); t.w = f2tf32(wv.w);
        *(uint4*)&Ws[k * WS + n4 * 4] = t;
    }

    // ---- phase 1: aggregate 64 node rows into aggS (row-major, tf32 bits) ----
    if (FIN == 128) {
        #pragma unroll 1
        for (int n = 0; n < 8; n++) {
            int vloc = wid * 8 + n;
            int v = blockIdx.x * 64 + vloc;
            float dv = g_dis[v];
            float sn = dv * dv;
            const float4* hr = (const float4*)(hin + (size_t)v * 128);
            float4 r = hr[lane];
            float4 acc;
            acc.x = sn * r.x; acc.y = sn * r.y; acc.z = sn * r.z; acc.w = sn * r.w;
            int e0 = g_row[v], e1 = g_row[v + 1];
            int e = e0;
            for (; e + 1 < e1; e += 2) {
                int   s0 = g_col[e],     s1 = g_col[e + 1];
                float m0 = g_en[e],      m1 = g_en[e + 1];
                float4 r0 = ((const float4*)(hin + (size_t)s0 * 128))[lane];
                float4 r1 = ((const float4*)(hin + (size_t)s1 * 128))[lane];
                acc.x += m0 * r0.x + m1 * r1.x;
                acc.y += m0 * r0.y + m1 * r1.y;
                acc.z += m0 * r0.z + m1 * r1.z;
                acc.w += m0 * r0.w + m1 * r1.w;
            }
            if (e < e1) {
                int   s0 = g_col[e];
                float m0 = g_en[e];
                float4 r0 = ((const float4*)(hin + (size_t)s0 * 128))[lane];
                acc.x += m0 * r0.x; acc.y += m0 * r0.y;
                acc.z += m0 * r0.z; acc.w += m0 * r0.w;
            }
            uint4 t;
            t.x = f2tf32(acc.x); t.y = f2tf32(acc.y);
            t.z = f2tf32(acc.z); t.w = f2tf32(acc.w);
            *(uint4*)&aggS[vloc * AS + lane * 4] = t;
        }
    } else { // FIN == 32: one float per lane
        #pragma unroll 1
        for (int n = 0; n < 8; n++) {
            int vloc = wid * 8 + n;
            int v = blockIdx.x * 64 + vloc;
            float dv = g_dis[v];
            float acc = dv * dv * hin[(size_t)v * 32 + lane];
            int e0 = g_row[v], e1 = g_row[v + 1];
            int e = e0;
            for (; e + 1 < e1; e += 2) {
                int   s0 = g_col[e],  s1 = g_col[e + 1];
                float m0 = g_en[e],   m1 = g_en[e + 1];
                acc += m0 * hin[(size_t)s0 * 32 + lane] + m1 * hin[(size_t)s1 * 32 + lane];
            }
            if (e < e1) acc += g_en[e] * hin[(size_t)g_col[e] * 32 + lane];
            ((uint32_t*)aggS)[vloc * AS + lane] = f2tf32(acc);
        }
    }
    __syncthreads();

    // ---- phase 2: tf32 MMA. Warp tile 32 rows x 32 cols (2 mi x 4 ni of m16n8k8). ----
    {
        const uint32_t* aggU = (const uint32_t*)aggS;
        const uint32_t* WsU  = (const uint32_t*)Ws;
        const int rowt = wid & 1;          // 2 row tiles of 32
        const int colt = wid >> 1;         // 4 col tiles of 32
        const int r_base = rowt * 32;
        const int n_base = colt * 32;
        const int group = lane >> 2;       // 0..7
        const int tig   = lane & 3;        // 0..3

        float C[2][4][4];
        #pragma unroll
        for (int mi = 0; mi < 2; mi++)
            #pragma unroll
            for (int ni = 0; ni < 4; ni++)
                #pragma unroll
                for (int j = 0; j < 4; j++) C[mi][ni][j] = 0.0f;

        #pragma unroll
        for (int k0 = 0; k0 < FIN; k0 += 8) {
            uint32_t a[2][4];
            #pragma unroll
            for (int mi = 0; mi < 2; mi++) {
                int r0 = r_base + mi * 16 + group;
                a[mi][0] = aggU[r0 * AS + k0 + tig];
                a[mi][1] = aggU[(r0 + 8) * AS + k0 + tig];
                a[mi][2] = aggU[r0 * AS + k0 + tig + 4];
                a[mi][3] = aggU[(r0 + 8) * AS + k0 + tig + 4];
            }
            #pragma unroll
            for (int ni = 0; ni < 4; ni++) {
                int nc = n_base + ni * 8 + group;
                uint32_t b0 = WsU[(k0 + tig) * WS + nc];
                uint32_t b1 = WsU[(k0 + tig + 4) * WS + nc];
                mma_tf32(C[0][ni], a[0][0], a[0][1], a[0][2], a[0][3], b0, b1);
                mma_tf32(C[1][ni], a[1][0], a[1][1], a[1][2], a[1][3], b0, b1);
            }
        }

        // ---- epilogue: bias + relu, float2 stores ----
        #pragma unroll
        for (int ni = 0; ni < 4; ni++) {
            int col = n_base + ni * 8 + 2 * tig;
            float2 bb = __ldg((const float2*)&b[col]);
            #pragma unroll
            for (int mi = 0; mi < 2; mi++) {
                int row0 = blockIdx.x * 64 + r_base + mi * 16 + group;
                float2 o0, o1;
                o0.x = fmaxf(C[mi][ni][0] + bb.x, 0.0f);
                o0.y = fmaxf(C[mi][ni][1] + bb.y, 0.0f);
                o1.x = fmaxf(C[mi][ni][2] + bb.x, 0.0f);
                o1.y = fmaxf(C[mi][ni][3] + bb.y, 0.0f);
                *(float2*)&hout[(size_t)row0 * 128 + col]       = o0;
                *(float2*)&hout[(size_t)(row0 + 8) * 128 + col] = o1;
            }
        }
    }
}

// ---------------- final: out = leakyrelu(h5 @ Wl + bl), one warp per node ----------------
__global__ void k_final(const float* __restrict__ Wl,
                        const float* __restrict__ bl,
                        float* __restrict__ out) {
    int warp = (blockIdx.x * blockDim.x + threadIdx.x) >> 5;   // exactly NN warps
    int lane = threadIdx.x & 31;
    float4 hv = *(const float4*)&g_hB[(size_t)warp * 128 + lane * 4];
    float4 w  = __ldg((const float4*)&Wl[lane * 4]);
    float s = hv.x * w.x + hv.y * w.y + hv.z * w.z + hv.w * w.w;
    #pragma unroll
    for (int off = 16; off; off >>= 1) s += __shfl_down_sync(0xFFFFFFFFu, s, off);
    if (lane == 0) {
        s += __ldg(bl);
        out[warp] = (s > 0.0f) ? s : 0.01f * s;
    }
}

// ---------------- launch ----------------
extern "C" void kernel_launch(void* const* d_in, const int* in_sizes, int n_in,
                              void* d_out, int out_size) {
    int ix = 0, ie = 1, iW1 = 2, ib1 = 3, iW2 = 4, ib2 = 5, iW3 = 6, ib3 = 7,
        iW4 = 8, ib4 = 9, iW5 = 10, ib5 = 11, iWl = 12, ibl = 13;
    if (n_in >= 14 && in_sizes[0] != 2 * NN) {
        if (in_sizes[0] == 64 && in_sizes[1] == 4096) {
            iW1 = 0; iW2 = 1; iW3 = 2; iW4 = 3; iW5 = 4; iWl = 5;
            ib1 = 6; ib2 = 7; ib3 = 8; ib4 = 9; ib5 = 10; ibl = 11;
            ie = 12; ix = 13;
        }
    }

    const float* x  = (const float*)d_in[ix];
    const void*  ei = d_in[ie];
    const float* W1 = (const float*)d_in[iW1];
    const float* b1 = (const float*)d_in[ib1];
    const float* W2 = (const float*)d_in[iW2];
    const float* b2 = (const float*)d_in[ib2];
    const float* W3 = (const float*)d_in[iW3];
    const float* b3 = (const float*)d_in[ib3];
    const float* W4 = (const float*)d_in[iW4];
    const float* b4 = (const float*)d_in[ib4];
    const float* W5 = (const float*)d_in[iW5];
    const float* b5 = (const float*)d_in[ib5];
    const float* Wl = (const float*)d_in[iWl];
    const float* bl = (const float*)d_in[ibl];
    float* out = (float*)d_out;

    const int sh32  = (32 * 136 + 64 * 36) * 4;    // 26,624 B
    const int sh128 = (128 * 136 + 64 * 132) * 4;  // 103,424 B
    cudaFuncSetAttribute(k_fused<32,  false>, cudaFuncAttributeMaxDynamicSharedMemorySize, sh32);
    cudaFuncSetAttribute(k_fused<128, true >, cudaFuncAttributeMaxDynamicSharedMemorySize, sh128);
    cudaFuncSetAttribute(k_fused<128, false>, cudaFuncAttributeMaxDynamicSharedMemorySize, sh128);

    // dtype probe + CSR + norms
    k_detect<<<1, 1>>>(ei);
    k_zero <<<(NN + 255) / 256, 256>>>();
    k_count<<<(EE + 255) / 256, 256>>>(ei);
    k_scanA<<<NBLK, SB>>>();
    k_scanB<<<1, SB>>>();
    k_scanC<<<(NN + 255) / 256, 256>>>();
    k_dis  <<<(NN + 255) / 256, 256>>>();
    k_fill <<<(EE + 255) / 256, 256>>>(ei);

    // layers (aggregate-then-GEMM reordering)
    k_layer1<<<(NN + 255) / 256, 256>>>(x, W1, b1);           // -> g_hB [N,32]
    k_fused<32,  false><<<3125, 256, sh32 >>>(W2, b2);        // hB -> hA [N,128]
    k_fused<128, true ><<<3125, 256, sh128>>>(W3, b3);        // hA -> hB
    k_fused<128, false><<<3125, 256, sh128>>>(W4, b4);        // hB -> hA
    k_fused<128, true ><<<3125, 256, sh128>>>(W5, b5);        // hA -> hB

    k_final<<<NN / 8, 256>>>(Wl, bl, out);                     // 8 warps/block, exact
}

// round 4
// speedup vs baseline: 1.5658x; 1.0493x over previous
#include <cuda_runtime.h>
#include <cstdint>

#define NN 200000
#define EE 640000
#define SB 512
#define NBLK 391   // ceil(NN / SB)

// ---------------- persistent device scratch (no allocations allowed) ----------------
__device__ float    g_hA[(size_t)NN * 128];
__device__ float    g_hB[(size_t)NN * 128];
__device__ uint32_t g_hC[(size_t)NN * 128];   // aggregated rows, tf32 bit patterns
__device__ float    g_dis[NN];
__device__ int      g_cnt[NN];
__device__ int      g_fill[NN];
__device__ int      g_row[NN + 1];
__device__ int      g_col[EE];
__device__ float    g_en[EE];
__device__ int      g_part[SB];
__device__ int      g_is64;

// ---------------- helpers ----------------
__device__ __forceinline__ uint32_t f2tf32(float f) {
    uint32_t u;
    asm("cvt.rna.tf32.f32 %0, %1;" : "=r"(u) : "f"(f));
    return u;
}

__device__ __forceinline__ void mma_tf32(float c[4],
                                         uint32_t a0, uint32_t a1, uint32_t a2, uint32_t a3,
                                         uint32_t b0, uint32_t b1) {
    asm volatile(
        "mma.sync.aligned.m16n8k8.row.col.f32.tf32.tf32.f32 "
        "{%0,%1,%2,%3}, {%4,%5,%6,%7}, {%8,%9}, {%0,%1,%2,%3};\n"
        : "+f"(c[0]), "+f"(c[1]), "+f"(c[2]), "+f"(c[3])
        : "r"(a0), "r"(a1), "r"(a2), "r"(a3), "r"(b0), "r"(b1));
}

// ---------------- edge dtype probe (int64 vs int32) ----------------
__global__ void k_detect(const void* ei) {
    const long long* p = (const long long*)ei;
    int ok = 1;
    #pragma unroll
    for (int i = 0; i < 4; i++) {
        long long v = p[i];
        if (v < 0 || v >= NN) ok = 0;
    }
    g_is64 = ok;
}

__device__ __forceinline__ int edge_at(const void* ei, int idx) {
    int v;
    if (g_is64) v = (int)((const long long*)ei)[idx];
    else        v = ((const int*)ei)[idx];
    return min(max(v, 0), NN - 1);
}

// ---------------- CSR build ----------------
__global__ void k_zero() {
    int i = blockIdx.x * blockDim.x + threadIdx.x;
    if (i < NN) { g_cnt[i] = 0; g_fill[i] = 0; }
}

__global__ void k_count(const void* __restrict__ ei) {
    int e = blockIdx.x * blockDim.x + threadIdx.x;
    if (e < EE) atomicAdd(&g_cnt[edge_at(ei, EE + e)], 1);
}

__global__ void k_scanA() {
    __shared__ int tmp[SB];
    int tid = threadIdx.x;
    int i = blockIdx.x * SB + tid;
    int v = (i < NN) ? g_cnt[i] : 0;
    tmp[tid] = v; __syncthreads();
    for (int off = 1; off < SB; off <<= 1) {
        int t = (tid >= off) ? tmp[tid - off] : 0;
        __syncthreads();
        if (tid >= off) tmp[tid] += t;
        __syncthreads();
    }
    if (i < NN) g_row[i + 1] = tmp[tid];
    if (tid == SB - 1) g_part[blockIdx.x] = tmp[tid];
}

__global__ void k_scanB() {
    __shared__ int tmp[SB];
    int tid = threadIdx.x;
    int v = (tid < NBLK) ? g_part[tid] : 0;
    tmp[tid] = v; __syncthreads();
    for (int off = 1; off < SB; off <<= 1) {
        int t = (tid >= off) ? tmp[tid - off] : 0;
        __syncthreads();
        if (tid >= off) tmp[tid] += t;
        __syncthreads();
    }
    if (tid < NBLK) g_part[tid] = tmp[tid] - v;   // exclusive block offsets
}

__global__ void k_scanC() {
    int i = blockIdx.x * blockDim.x + threadIdx.x;
    if (i < NN) {
        g_row[i + 1] += g_part[i / SB];
        if (i == 0) g_row[0] = 0;
    }
}

__global__ void k_dis() {
    int i = blockIdx.x * blockDim.x + threadIdx.x;
    if (i < NN) g_dis[i] = rsqrtf((float)g_cnt[i] + 1.0f);
}

__global__ void k_fill(const void* __restrict__ ei) {
    int e = blockIdx.x * blockDim.x + threadIdx.x;
    if (e < EE) {
        int d = edge_at(ei, EE + e);
        int s = edge_at(ei, e);
        int p = g_row[d] + atomicAdd(&g_fill[d], 1);
        g_col[p] = s;
        g_en[p] = g_dis[s] * g_dis[d];
    }
}

// ---------------- layer 1: aggregate x (2 feats) then [N,2]@[2,32]+b1, relu -> g_hB ----------------
__global__ void k_layer1(const float* __restrict__ x,
                         const float* __restrict__ W1,
                         const float* __restrict__ b1) {
    __shared__ float w[64], bb[32];
    if (threadIdx.x < 64) w[threadIdx.x] = W1[threadIdx.x];
    if (threadIdx.x < 32) bb[threadIdx.x] = b1[threadIdx.x];
    __syncthreads();
    int v = blockIdx.x * blockDim.x + threadIdx.x;
    if (v >= NN) return;
    float dv = g_dis[v];
    float a0 = dv * dv * x[2 * v];
    float a1 = dv * dv * x[2 * v + 1];
    int e0 = g_row[v], e1 = g_row[v + 1];
    for (int e = e0; e < e1; e++) {
        int s = g_col[e];
        float nm = g_en[e];
        a0 += nm * x[2 * s];
        a1 += nm * x[2 * s + 1];
    }
    float* out = &g_hB[(size_t)v * 32];
    #pragma unroll
    for (int c = 0; c < 32; c++) {
        float r = a0 * w[c] + a1 * w[32 + c] + bb[c];
        out[c] = fmaxf(r, 0.0f);
    }
}

// ---------------- aggregation, 128 feats: warp per node, full occupancy, unroll-4 gathers ----------------
template <bool IN_A>
__global__ void __launch_bounds__(256) k_agg128() {
    const float* hin = IN_A ? g_hA : g_hB;
    int v = blockIdx.x * 8 + (threadIdx.x >> 5);   // 25000 blocks x 8 warps = NN exactly
    int lane = threadIdx.x & 31;

    float dv = g_dis[v];
    float sn = dv * dv;
    float4 r = __ldg((const float4*)(hin + (size_t)v * 128) + lane);
    float4 acc;
    acc.x = sn * r.x; acc.y = sn * r.y; acc.z = sn * r.z; acc.w = sn * r.w;

    int e  = g_row[v];
    int e1 = g_row[v + 1];
    for (; e + 3 < e1; e += 4) {
        int   s0 = g_col[e],   s1 = g_col[e+1], s2 = g_col[e+2], s3 = g_col[e+3];
        float m0 = g_en[e],    m1 = g_en[e+1],  m2 = g_en[e+2],  m3 = g_en[e+3];
        float4 r0 = __ldg((const float4*)(hin + (size_t)s0 * 128) + lane);
        float4 r1 = __ldg((const float4*)(hin + (size_t)s1 * 128) + lane);
        float4 r2 = __ldg((const float4*)(hin + (size_t)s2 * 128) + lane);
        float4 r3 = __ldg((const float4*)(hin + (size_t)s3 * 128) + lane);
        acc.x += m0*r0.x + m1*r1.x + m2*r2.x + m3*r3.x;
        acc.y += m0*r0.y + m1*r1.y + m2*r2.y + m3*r3.y;
        acc.z += m0*r0.z + m1*r1.z + m2*r2.z + m3*r3.z;
        acc.w += m0*r0.w + m1*r1.w + m2*r2.w + m3*r3.w;
    }
    for (; e < e1; e++) {
        int   s0 = g_col[e];
        float m0 = g_en[e];
        float4 r0 = __ldg((const float4*)(hin + (size_t)s0 * 128) + lane);
        acc.x += m0*r0.x; acc.y += m0*r0.y; acc.z += m0*r0.z; acc.w += m0*r0.w;
    }

    uint4 t;
    t.x = f2tf32(acc.x); t.y = f2tf32(acc.y);
    t.z = f2tf32(acc.z); t.w = f2tf32(acc.w);
    *((uint4*)(g_hC + (size_t)v * 128) + lane) = t;
}

// ---------------- aggregation, 32 feats: warp per node, one float per lane, unroll-4 ----------------
__global__ void __launch_bounds__(256) k_agg32() {
    const float* hin = g_hB;
    int v = blockIdx.x * 8 + (threadIdx.x >> 5);
    int lane = threadIdx.x & 31;

    float dv = g_dis[v];
    float acc = dv * dv * __ldg(hin + (size_t)v * 32 + lane);

    int e  = g_row[v];
    int e1 = g_row[v + 1];
    for (; e + 3 < e1; e += 4) {
        int   s0 = g_col[e],   s1 = g_col[e+1], s2 = g_col[e+2], s3 = g_col[e+3];
        float m0 = g_en[e],    m1 = g_en[e+1],  m2 = g_en[e+2],  m3 = g_en[e+3];
        float r0 = __ldg(hin + (size_t)s0 * 32 + lane);
        float r1 = __ldg(hin + (size_t)s1 * 32 + lane);
        float r2 = __ldg(hin + (size_t)s2 * 32 + lane);
        float r3 = __ldg(hin + (size_t)s3 * 32 + lane);
        acc += m0*r0 + m1*r1 + m2*r2 + m3*r3;
    }
    for (; e < e1; e++)
        acc += g_en[e] * __ldg(hin + (size_t)g_col[e] * 32 + lane);

    g_hC[(size_t)v * 32 + lane] = f2tf32(acc);
}

// ---------------- GEMM: [64,FIN] (tf32 bits in g_hC) @ [FIN,128] + b, relu ----------------
// 256 threads, 3125 blocks. A-fragments straight from global (L1-reused by 4 col-warps),
// W in smem stride 136 (bank 8k+n distinct -> conflict-free).
template <int FIN, bool OUT_A>
__global__ void __launch_bounds__(256) k_gemm(const float* __restrict__ W,
                                              const float* __restrict__ b) {
    constexpr int WS = 136;
    extern __shared__ float smem[];
    float* Ws = smem;                       // [FIN][WS], tf32 bit patterns
    float* hout = OUT_A ? g_hA : g_hB;

    const int tid  = threadIdx.x;
    const int wid  = tid >> 5;
    const int lane = tid & 31;

    // load W into shared, converting to tf32
    for (int idx4 = tid; idx4 < FIN * 32; idx4 += 256) {
        int k  = idx4 >> 5;
        int n4 = idx4 & 31;
        float4 wv = ((const float4*)W)[idx4];
        uint4 t;
        t.x = f2tf32(wv.x); t.y = f2tf32(wv.y);
        t.z = f2tf32(wv.z); t.w = f2tf32(wv.w);
        *(uint4*)&Ws[k * WS + n4 * 4] = t;
    }
    __syncthreads();

    const uint32_t* A = g_hC + (size_t)blockIdx.x * 64 * FIN;
    const uint32_t* WsU = (const uint32_t*)Ws;

    const int rowt = wid & 1;          // 2 row tiles of 32
    const int colt = wid >> 1;         // 4 col tiles of 32
    const int r_base = rowt * 32;
    const int n_base = colt * 32;
    const int group = lane >> 2;       // 0..7
    const int tig   = lane & 3;        // 0..3

    float C[2][4][4];
    #pragma unroll
    for (int mi = 0; mi < 2; mi++)
        #pragma unroll
        for (int ni = 0; ni < 4; ni++)
            #pragma unroll
            for (int j = 0; j < 4; j++) C[mi][ni][j] = 0.0f;

    #pragma unroll
    for (int k0 = 0; k0 < FIN; k0 += 8) {
        uint32_t a[2][4];
        #pragma unroll
        for (int mi = 0; mi < 2; mi++) {
            int r0 = r_base + mi * 16 + group;
            a[mi][0] = __ldg(&A[(size_t)r0 * FIN + k0 + tig]);
            a[mi][1] = __ldg(&A[(size_t)(r0 + 8) * FIN + k0 + tig]);
            a[mi][2] = __ldg(&A[(size_t)r0 * FIN + k0 + tig + 4]);
            a[mi][3] = __ldg(&A[(size_t)(r0 + 8) * FIN + k0 + tig + 4]);
        }
        #pragma unroll
        for (int ni = 0; ni < 4; ni++) {
            int nc = n_base + ni * 8 + group;
            uint32_t b0 = WsU[(k0 + tig) * WS + nc];
            uint32_t b1 = WsU[(k0 + tig + 4) * WS + nc];
            mma_tf32(C[0][ni], a[0][0], a[0][1], a[0][2], a[0][3], b0, b1);
            mma_tf32(C[1][ni], a[1][0], a[1][1], a[1][2], a[1][3], b0, b1);
        }
    }

    // epilogue: bias + relu, float2 stores
    #pragma unroll
    for (int ni = 0; ni < 4; ni++) {
        int col = n_base + ni * 8 + 2 * tig;
        float2 bb = __ldg((const float2*)&b[col]);
        #pragma unroll
        for (int mi = 0; mi < 2; mi++) {
            int row0 = blockIdx.x * 64 + r_base + mi * 16 + group;
            float2 o0, o1;
            o0.x = fmaxf(C[mi][ni][0] + bb.x, 0.0f);
            o0.y = fmaxf(C[mi][ni][1] + bb.y, 0.0f);
            o1.x = fmaxf(C[mi][ni][2] + bb.x, 0.0f);
            o1.y = fmaxf(C[mi][ni][3] + bb.y, 0.0f);
            *(float2*)&hout[(size_t)row0 * 128 + col]       = o0;
            *(float2*)&hout[(size_t)(row0 + 8) * 128 + col] = o1;
        }
    }
}

// ---------------- final: out = leakyrelu(h5 @ Wl + bl), one warp per node ----------------
__global__ void k_final(const float* __restrict__ Wl,
                        const float* __restrict__ bl,
                        float* __restrict__ out) {
    int warp = (blockIdx.x * blockDim.x + threadIdx.x) >> 5;   // exactly NN warps
    int lane = threadIdx.x & 31;
    float4 hv = *(const float4*)&g_hB[(size_t)warp * 128 + lane * 4];
    float4 w  = __ldg((const float4*)&Wl[lane * 4]);
    float s = hv.x * w.x + hv.y * w.y + hv.z * w.z + hv.w * w.w;
    #pragma unroll
    for (int off = 16; off; off >>= 1) s += __shfl_down_sync(0xFFFFFFFFu, s, off);
    if (lane == 0) {
        s += __ldg(bl);
        out[warp] = (s > 0.0f) ? s : 0.01f * s;
    }
}

// ---------------- launch ----------------
extern "C" void kernel_launch(void* const* d_in, const int* in_sizes, int n_in,
                              void* d_out, int out_size) {
    int ix = 0, ie = 1, iW1 = 2, ib1 = 3, iW2 = 4, ib2 = 5, iW3 = 6, ib3 = 7,
        iW4 = 8, ib4 = 9, iW5 = 10, ib5 = 11, iWl = 12, ibl = 13;
    if (n_in >= 14 && in_sizes[0] != 2 * NN) {
        if (in_sizes[0] == 64 && in_sizes[1] == 4096) {
            iW1 = 0; iW2 = 1; iW3 = 2; iW4 = 3; iW5 = 4; iWl = 5;
            ib1 = 6; ib2 = 7; ib3 = 8; ib4 = 9; ib5 = 10; ibl = 11;
            ie = 12; ix = 13;
        }
    }

    const float* x  = (const float*)d_in[ix];
    const void*  ei = d_in[ie];
    const float* W1 = (const float*)d_in[iW1];
    const float* b1 = (const float*)d_in[ib1];
    const float* W2 = (const float*)d_in[iW2];
    const float* b2 = (const float*)d_in[ib2];
    const float* W3 = (const float*)d_in[iW3];
    const float* b3 = (const float*)d_in[ib3];
    const float* W4 = (const float*)d_in[iW4];
    const float* b4 = (const float*)d_in[ib4];
    const float* W5 = (const float*)d_in[iW5];
    const float* b5 = (const float*)d_in[ib5];
    const float* Wl = (const float*)d_in[iWl];
    const float* bl = (const float*)d_in[ibl];
    float* out = (float*)d_out;

    const int sh32  = 32  * 136 * 4;   // 17,408 B
    const int sh128 = 128 * 136 * 4;   // 69,632 B
    cudaFuncSetAttribute(k_gemm<32,  true >, cudaFuncAttributeMaxDynamicSharedMemorySize, sh32);
    cudaFuncSetAttribute(k_gemm<128, true >, cudaFuncAttributeMaxDynamicSharedMemorySize, sh128);
    cudaFuncSetAttribute(k_gemm<128, false>, cudaFuncAttributeMaxDynamicSharedMemorySize, sh128);

    // dtype probe + CSR + norms
    k_detect<<<1, 1>>>(ei);
    k_zero <<<(NN + 255) / 256, 256>>>();
    k_count<<<(EE + 255) / 256, 256>>>(ei);
    k_scanA<<<NBLK, SB>>>();
    k_scanB<<<1, SB>>>();
    k_scanC<<<(NN + 255) / 256, 256>>>();
    k_dis  <<<(NN + 255) / 256, 256>>>();
    k_fill <<<(EE + 255) / 256, 256>>>(ei);

    // layers: agg (full-occupancy gather) then tf32 MMA gemm
    k_layer1<<<(NN + 255) / 256, 256>>>(x, W1, b1);            // x -> hB [N,32]
    k_agg32 <<<NN / 8, 256>>>();                               // hB -> C [N,32]
    k_gemm<32,  true ><<<3125, 256, sh32 >>>(W2, b2);          // C -> hA [N,128]
    k_agg128<true ><<<NN / 8, 256>>>();                        // hA -> C
    k_gemm<128, false><<<3125, 256, sh128>>>(W3, b3);          // C -> hB
    k_agg128<false><<<NN / 8, 256>>>();                        // hB -> C
    k_gemm<128, true ><<<3125, 256, sh128>>>(W4, b4);          // C -> hA
    k_agg128<true ><<<NN / 8, 256>>>();                        // hA -> C
    k_gemm<128, false><<<3125, 256, sh128>>>(W5, b5);          // C -> hB

    k_final<<<NN / 8, 256>>>(Wl, bl, out);                     // 8 warps/block, exact
}

// round 5
// speedup vs baseline: 1.7461x; 1.1152x over previous
#include <cuda_runtime.h>
#include <cuda_bf16.h>
#include <cstdint>

#define NN 200000
#define EE 640000
#define SB 512
#define NBLK 391   // ceil(NN / SB)

// ---------------- persistent device scratch (no allocations allowed) ----------------
// h buffers: packed bf16, 64 uint32 per 128-feat row (32-feat rows use stride 16)
__device__ uint32_t g_hA[(size_t)NN * 64];
__device__ uint32_t g_hB[(size_t)NN * 64];
__device__ uint32_t g_hC[(size_t)NN * 128];   // aggregated rows, tf32 bit patterns
__device__ float    g_dis[NN];
__device__ int      g_cnt[NN];
__device__ int      g_fill[NN];
__device__ int      g_row[NN + 1];
__device__ int      g_col[EE];
__device__ float    g_en[EE];
__device__ int      g_part[SB];
__device__ int      g_is64;

// ---------------- helpers ----------------
__device__ __forceinline__ uint32_t f2tf32(float f) {
    uint32_t u;
    asm("cvt.rna.tf32.f32 %0, %1;" : "=r"(u) : "f"(f));
    return u;
}

__device__ __forceinline__ uint32_t pack_bf16(float lo, float hi) {
    __nv_bfloat162 h = __floats2bfloat162_rn(lo, hi);   // .x = lo (low 16 bits)
    return *reinterpret_cast<uint32_t*>(&h);
}

__device__ __forceinline__ float2 unpack_bf16(uint32_t u) {
    __nv_bfloat162 h = *reinterpret_cast<__nv_bfloat162*>(&u);
    return __bfloat1622float2(h);                        // .x = low half
}

__device__ __forceinline__ void mma_tf32(float c[4],
                                         uint32_t a0, uint32_t a1, uint32_t a2, uint32_t a3,
                                         uint32_t b0, uint32_t b1) {
    asm volatile(
        "mma.sync.aligned.m16n8k8.row.col.f32.tf32.tf32.f32 "
        "{%0,%1,%2,%3}, {%4,%5,%6,%7}, {%8,%9}, {%0,%1,%2,%3};\n"
        : "+f"(c[0]), "+f"(c[1]), "+f"(c[2]), "+f"(c[3])
        : "r"(a0), "r"(a1), "r"(a2), "r"(a3), "r"(b0), "r"(b1));
}

// ---------------- edge dtype probe (int64 vs int32) ----------------
__global__ void k_detect(const void* ei) {
    const long long* p = (const long long*)ei;
    int ok = 1;
    #pragma unroll
    for (int i = 0; i < 4; i++) {
        long long v = p[i];
        if (v < 0 || v >= NN) ok = 0;
    }
    g_is64 = ok;
}

__device__ __forceinline__ int edge_at(const void* ei, int idx) {
    int v;
    if (g_is64) v = (int)((const long long*)ei)[idx];
    else        v = ((const int*)ei)[idx];
    return min(max(v, 0), NN - 1);
}

// ---------------- CSR build ----------------
__global__ void k_zero() {
    int i = blockIdx.x * blockDim.x + threadIdx.x;
    if (i < NN) { g_cnt[i] = 0; g_fill[i] = 0; }
}

__global__ void k_count(const void* __restrict__ ei) {
    int e = blockIdx.x * blockDim.x + threadIdx.x;
    if (e < EE) atomicAdd(&g_cnt[edge_at(ei, EE + e)], 1);
}

__global__ void k_scanA() {
    __shared__ int tmp[SB];
    int tid = threadIdx.x;
    int i = blockIdx.x * SB + tid;
    int v = (i < NN) ? g_cnt[i] : 0;
    tmp[tid] = v; __syncthreads();
    for (int off = 1; off < SB; off <<= 1) {
        int t = (tid >= off) ? tmp[tid - off] : 0;
        __syncthreads();
        if (tid >= off) tmp[tid] += t;
        __syncthreads();
    }
    if (i < NN) g_row[i + 1] = tmp[tid];
    if (tid == SB - 1) g_part[blockIdx.x] = tmp[tid];
}

__global__ void k_scanB() {
    __shared__ int tmp[SB];
    int tid = threadIdx.x;
    int v = (tid < NBLK) ? g_part[tid] : 0;
    tmp[tid] = v; __syncthreads();
    for (int off = 1; off < SB; off <<= 1) {
        int t = (tid >= off) ? tmp[tid - off] : 0;
        __syncthreads();
        if (tid >= off) tmp[tid] += t;
        __syncthreads();
    }
    if (tid < NBLK) g_part[tid] = tmp[tid] - v;   // exclusive block offsets
}

__global__ void k_scanC() {   // also computes g_dis (merged)
    int i = blockIdx.x * blockDim.x + threadIdx.x;
    if (i < NN) {
        g_row[i + 1] += g_part[i / SB];
        if (i == 0) g_row[0] = 0;
        g_dis[i] = rsqrtf((float)g_cnt[i] + 1.0f);
    }
}

__global__ void k_fill(const void* __restrict__ ei) {
    int e = blockIdx.x * blockDim.x + threadIdx.x;
    if (e < EE) {
        int d = edge_at(ei, EE + e);
        int s = edge_at(ei, e);
        int p = g_row[d] + atomicAdd(&g_fill[d], 1);
        g_col[p] = s;
        g_en[p] = g_dis[s] * g_dis[d];
    }
}

// ---------------- layer 1: aggregate x (2 feats) then [N,2]@[2,32]+b1, relu -> g_hB (bf16) ----------------
__global__ void k_layer1(const float* __restrict__ x,
                         const float* __restrict__ W1,
                         const float* __restrict__ b1) {
    __shared__ float w[64], bb[32];
    if (threadIdx.x < 64) w[threadIdx.x] = W1[threadIdx.x];
    if (threadIdx.x < 32) bb[threadIdx.x] = b1[threadIdx.x];
    __syncthreads();
    int v = blockIdx.x * blockDim.x + threadIdx.x;
    if (v >= NN) return;
    float dv = g_dis[v];
    float a0 = dv * dv * x[2 * v];
    float a1 = dv * dv * x[2 * v + 1];
    int e0 = g_row[v], e1 = g_row[v + 1];
    for (int e = e0; e < e1; e++) {
        int s = g_col[e];
        float nm = g_en[e];
        a0 += nm * x[2 * s];
        a1 += nm * x[2 * s + 1];
    }
    uint32_t* out = &g_hB[(size_t)v * 16];
    #pragma unroll
    for (int j = 0; j < 16; j++) {
        float r0 = fmaxf(a0 * w[2 * j]     + a1 * w[32 + 2 * j]     + bb[2 * j],     0.0f);
        float r1 = fmaxf(a0 * w[2 * j + 1] + a1 * w[32 + 2 * j + 1] + bb[2 * j + 1], 0.0f);
        out[j] = pack_bf16(r0, r1);
    }
}

// ---------------- aggregation, 128 feats (bf16 rows, 256B): warp per node, unroll-4 gathers ----------------
template <bool IN_A>
__global__ void __launch_bounds__(256) k_agg128() {
    const uint32_t* hin = IN_A ? g_hA : g_hB;
    int v = blockIdx.x * 8 + (threadIdx.x >> 5);   // 25000 blocks x 8 warps = NN exactly
    int lane = threadIdx.x & 31;

    float dv = g_dis[v];
    float sn = dv * dv;
    uint2 u = __ldg((const uint2*)(hin + (size_t)v * 64) + lane);
    float2 p0 = unpack_bf16(u.x), p1 = unpack_bf16(u.y);
    float a0 = sn * p0.x, a1 = sn * p0.y, a2 = sn * p1.x, a3 = sn * p1.y;

    int e  = g_row[v];
    int e1 = g_row[v + 1];
    for (; e + 3 < e1; e += 4) {
        int   s0 = g_col[e],   s1 = g_col[e+1], s2 = g_col[e+2], s3 = g_col[e+3];
        float m0 = g_en[e],    m1 = g_en[e+1],  m2 = g_en[e+2],  m3 = g_en[e+3];
        uint2 u0 = __ldg((const uint2*)(hin + (size_t)s0 * 64) + lane);
        uint2 u1 = __ldg((const uint2*)(hin + (size_t)s1 * 64) + lane);
        uint2 u2 = __ldg((const uint2*)(hin + (size_t)s2 * 64) + lane);
        uint2 u3 = __ldg((const uint2*)(hin + (size_t)s3 * 64) + lane);
        float2 q;
        q = unpack_bf16(u0.x); a0 += m0*q.x; a1 += m0*q.y;
        q = unpack_bf16(u0.y); a2 += m0*q.x; a3 += m0*q.y;
        q = unpack_bf16(u1.x); a0 += m1*q.x; a1 += m1*q.y;
        q = unpack_bf16(u1.y); a2 += m1*q.x; a3 += m1*q.y;
        q = unpack_bf16(u2.x); a0 += m2*q.x; a1 += m2*q.y;
        q = unpack_bf16(u2.y); a2 += m2*q.x; a3 += m2*q.y;
        q = unpack_bf16(u3.x); a0 += m3*q.x; a1 += m3*q.y;
        q = unpack_bf16(u3.y); a2 += m3*q.x; a3 += m3*q.y;
    }
    for (; e < e1; e++) {
        int   s0 = g_col[e];
        float m0 = g_en[e];
        uint2 u0 = __ldg((const uint2*)(hin + (size_t)s0 * 64) + lane);
        float2 q;
        q = unpack_bf16(u0.x); a0 += m0*q.x; a1 += m0*q.y;
        q = unpack_bf16(u0.y); a2 += m0*q.x; a3 += m0*q.y;
    }

    uint4 t;
    t.x = f2tf32(a0); t.y = f2tf32(a1); t.z = f2tf32(a2); t.w = f2tf32(a3);
    ((uint4*)(g_hC + (size_t)v * 128))[lane] = t;
}

// ---------------- aggregation, 32 feats (bf16, 64B rows): warp per node, lanes 0..15 active ----------------
__global__ void __launch_bounds__(256) k_agg32() {
    const uint32_t* hin = g_hB;
    int v = blockIdx.x * 8 + (threadIdx.x >> 5);
    int lane = threadIdx.x & 31;
    if (lane >= 16) return;

    float dv = g_dis[v];
    float sn = dv * dv;
    float2 p = unpack_bf16(__ldg(hin + (size_t)v * 16 + lane));
    float a0 = sn * p.x, a1 = sn * p.y;

    int e  = g_row[v];
    int e1 = g_row[v + 1];
    for (; e + 3 < e1; e += 4) {
        int   s0 = g_col[e],   s1 = g_col[e+1], s2 = g_col[e+2], s3 = g_col[e+3];
        float m0 = g_en[e],    m1 = g_en[e+1],  m2 = g_en[e+2],  m3 = g_en[e+3];
        float2 q0 = unpack_bf16(__ldg(hin + (size_t)s0 * 16 + lane));
        float2 q1 = unpack_bf16(__ldg(hin + (size_t)s1 * 16 + lane));
        float2 q2 = unpack_bf16(__ldg(hin + (size_t)s2 * 16 + lane));
        float2 q3 = unpack_bf16(__ldg(hin + (size_t)s3 * 16 + lane));
        a0 += m0*q0.x + m1*q1.x + m2*q2.x + m3*q3.x;
        a1 += m0*q0.y + m1*q1.y + m2*q2.y + m3*q3.y;
    }
    for (; e < e1; e++) {
        float2 q = unpack_bf16(__ldg(hin + (size_t)g_col[e] * 16 + lane));
        a0 += g_en[e] * q.x;
        a1 += g_en[e] * q.y;
    }

    g_hC[(size_t)v * 32 + 2 * lane]     = f2tf32(a0);
    g_hC[(size_t)v * 32 + 2 * lane + 1] = f2tf32(a1);
}

// ---------------- GEMM: [64,FIN] (tf32 bits in g_hC) @ [FIN,128] + b, relu -> bf16 h ----------------
// 256 threads, 3125 blocks. A-fragments straight from global (L1-reused by 4 col-warps),
// W in smem stride 136 (bank 8k+n distinct -> conflict-free).
template <int FIN, bool OUT_A>
__global__ void __launch_bounds__(256) k_gemm(const float* __restrict__ W,
                                              const float* __restrict__ b) {
    constexpr int WS = 136;
    extern __shared__ float smem[];
    float* Ws = smem;                       // [FIN][WS], tf32 bit patterns
    uint32_t* hout = OUT_A ? g_hA : g_hB;

    const int tid  = threadIdx.x;
    const int wid  = tid >> 5;
    const int lane = tid & 31;

    // load W into shared, converting to tf32
    for (int idx4 = tid; idx4 < FIN * 32; idx4 += 256) {
        int k  = idx4 >> 5;
        int n4 = idx4 & 31;
        float4 wv = ((const float4*)W)[idx4];
        uint4 t;
        t.x = f2tf32(wv.x); t.y = f2tf32(wv.y);
        t.z = f2tf32(wv.z); t.w = f2tf32(wv.w);
        *(uint4*)&Ws[k * WS + n4 * 4] = t;
    }
    __syncthreads();

    const uint32_t* A = g_hC + (size_t)blockIdx.x * 64 * FIN;
    const uint32_t* WsU = (const uint32_t*)Ws;

    const int rowt = wid & 1;          // 2 row tiles of 32
    const int colt = wid >> 1;         // 4 col tiles of 32
    const int r_base = rowt * 32;
    const int n_base = colt * 32;
    const int group = lane >> 2;       // 0..7
    const int tig   = lane & 3;        // 0..3

    float C[2][4][4];
    #pragma unroll
    for (int mi = 0; mi < 2; mi++)
        #pragma unroll
        for (int ni = 0; ni < 4; ni++)
            #pragma unroll
            for (int j = 0; j < 4; j++) C[mi][ni][j] = 0.0f;

    #pragma unroll
    for (int k0 = 0; k0 < FIN; k0 += 8) {
        uint32_t a[2][4];
        #pragma unroll
        for (int mi = 0; mi < 2; mi++) {
            int r0 = r_base + mi * 16 + group;
            a[mi][0] = __ldg(&A[(size_t)r0 * FIN + k0 + tig]);
            a[mi][1] = __ldg(&A[(size_t)(r0 + 8) * FIN + k0 + tig]);
            a[mi][2] = __ldg(&A[(size_t)r0 * FIN + k0 + tig + 4]);
            a[mi][3] = __ldg(&A[(size_t)(r0 + 8) * FIN + k0 + tig + 4]);
        }
        #pragma unroll
        for (int ni = 0; ni < 4; ni++) {
            int nc = n_base + ni * 8 + group;
            uint32_t b0 = WsU[(k0 + tig) * WS + nc];
            uint32_t b1 = WsU[(k0 + tig + 4) * WS + nc];
            mma_tf32(C[0][ni], a[0][0], a[0][1], a[0][2], a[0][3], b0, b1);
            mma_tf32(C[1][ni], a[1][0], a[1][1], a[1][2], a[1][3], b0, b1);
        }
    }

    // epilogue: bias + relu, pack to bf16x2 (cols 2tig, 2tig+1 are adjacent)
    #pragma unroll
    for (int ni = 0; ni < 4; ni++) {
        int col = n_base + ni * 8 + 2 * tig;
        float2 bb = __ldg((const float2*)&b[col]);
        #pragma unroll
        for (int mi = 0; mi < 2; mi++) {
            int row0 = blockIdx.x * 64 + r_base + mi * 16 + group;
            float o00 = fmaxf(C[mi][ni][0] + bb.x, 0.0f);
            float o01 = fmaxf(C[mi][ni][1] + bb.y, 0.0f);
            float o10 = fmaxf(C[mi][ni][2] + bb.x, 0.0f);
            float o11 = fmaxf(C[mi][ni][3] + bb.y, 0.0f);
            hout[(size_t)row0 * 64 + (col >> 1)]       = pack_bf16(o00, o01);
            hout[(size_t)(row0 + 8) * 64 + (col >> 1)] = pack_bf16(o10, o11);
        }
    }
}

// ---------------- final: out = leakyrelu(h5 @ Wl + bl), one warp per node ----------------
__global__ void k_final(const float* __restrict__ Wl,
                        const float* __restrict__ bl,
                        float* __restrict__ out) {
    int warp = (blockIdx.x * blockDim.x + threadIdx.x) >> 5;   // exactly NN warps
    int lane = threadIdx.x & 31;
    uint2 u = __ldg((const uint2*)(g_hB + (size_t)warp * 64) + lane);
    float2 p0 = unpack_bf16(u.x), p1 = unpack_bf16(u.y);
    float4 w  = __ldg((const float4*)&Wl[lane * 4]);
    float s = p0.x * w.x + p0.y * w.y + p1.x * w.z + p1.y * w.w;
    #pragma unroll
    for (int off = 16; off; off >>= 1) s += __shfl_down_sync(0xFFFFFFFFu, s, off);
    if (lane == 0) {
        s += __ldg(bl);
        out[warp] = (s > 0.0f) ? s : 0.01f * s;
    }
}

// ---------------- launch ----------------
extern "C" void kernel_launch(void* const* d_in, const int* in_sizes, int n_in,
                              void* d_out, int out_size) {
    int ix = 0, ie = 1, iW1 = 2, ib1 = 3, iW2 = 4, ib2 = 5, iW3 = 6, ib3 = 7,
        iW4 = 8, ib4 = 9, iW5 = 10, ib5 = 11, iWl = 12, ibl = 13;
    if (n_in >= 14 && in_sizes[0] != 2 * NN) {
        if (in_sizes[0] == 64 && in_sizes[1] == 4096) {
            iW1 = 0; iW2 = 1; iW3 = 2; iW4 = 3; iW5 = 4; iWl = 5;
            ib1 = 6; ib2 = 7; ib3 = 8; ib4 = 9; ib5 = 10; ibl = 11;
            ie = 12; ix = 13;
        }
    }

    const float* x  = (const float*)d_in[ix];
    const void*  ei = d_in[ie];
    const float* W1 = (const float*)d_in[iW1];
    const float* b1 = (const float*)d_in[ib1];
    const float* W2 = (const float*)d_in[iW2];
    const float* b2 = (const float*)d_in[ib2];
    const float* W3 = (const float*)d_in[iW3];
    const float* b3 = (const float*)d_in[ib3];
    const float* W4 = (const float*)d_in[iW4];
    const float* b4 = (const float*)d_in[ib4];
    const float* W5 = (const float*)d_in[iW5];
    const float* b5 = (const float*)d_in[ib5];
    const float* Wl = (const float*)d_in[iWl];
    const float* bl = (const float*)d_in[ibl];
    float* out = (float*)d_out;

    const int sh32  = 32  * 136 * 4;   // 17,408 B
    const int sh128 = 128 * 136 * 4;   // 69,632 B
    cudaFuncSetAttribute(k_gemm<32,  true >, cudaFuncAttributeMaxDynamicSharedMemorySize, sh32);
    cudaFuncSetAttribute(k_gemm<128, true >, cudaFuncAttributeMaxDynamicSharedMemorySize, sh128);
    cudaFuncSetAttribute(k_gemm<128, false>, cudaFuncAttributeMaxDynamicSharedMemorySize, sh128);

    // dtype probe + CSR + norms
    k_detect<<<1, 1>>>(ei);
    k_zero <<<(NN + 255) / 256, 256>>>();
    k_count<<<(EE + 255) / 256, 256>>>(ei);
    k_scanA<<<NBLK, SB>>>();
    k_scanB<<<1, SB>>>();
    k_scanC<<<(NN + 255) / 256, 256>>>();   // + g_dis
    k_fill <<<(EE + 255) / 256, 256>>>(ei);

    // layers: agg (bf16 gathers, fp32 accum, tf32 out) then tf32 MMA gemm (bf16 out)
    k_layer1<<<(NN + 255) / 256, 256>>>(x, W1, b1);            // x -> hB [N,32] bf16
    k_agg32 <<<NN / 8, 256>>>();                               // hB -> C [N,32] tf32
    k_gemm<32,  true ><<<3125, 256, sh32 >>>(W2, b2);          // C -> hA [N,128] bf16
    k_agg128<true ><<<NN / 8, 256>>>();                        // hA -> C
    k_gemm<128, false><<<3125, 256, sh128>>>(W3, b3);          // C -> hB
    k_agg128<false><<<NN / 8, 256>>>();                        // hB -> C
    k_gemm<128, true ><<<3125, 256, sh128>>>(W4, b4);          // C -> hA
    k_agg128<true ><<<NN / 8, 256>>>();                        // hA -> C
    k_gemm<128, false><<<3125, 256, sh128>>>(W5, b5);          // C -> hB

    k_final<<<NN / 8, 256>>>(Wl, bl, out);                     // 8 warps/block, exact
}

// round 6
// speedup vs baseline: 2.0462x; 1.1718x over previous
#include <cuda_runtime.h>
#include <cuda_bf16.h>
#include <cstdint>

#define NN 200000
#define EE 640000
#define SB 512
#define NBLK 391   // ceil(NN / SB)

// ---------------- persistent device scratch (no allocations allowed) ----------------
// h buffers: packed bf16, 64 uint32 per 128-feat row (32-feat rows use stride 16)
__device__ uint32_t g_hA[(size_t)NN * 64];
__device__ uint32_t g_hB[(size_t)NN * 64];
__device__ uint32_t g_hC[(size_t)NN * 128];   // aggregated rows, tf32 bit patterns
__device__ float    g_dis[NN];
__device__ int      g_cnt[NN];
__device__ int      g_fill[NN];
__device__ int      g_row[NN + 1];
__device__ int      g_col[EE];
__device__ float    g_en[EE];
__device__ int      g_part[SB];
__device__ int      g_is64;

// ---------------- helpers ----------------
__device__ __forceinline__ uint32_t f2tf32(float f) {
    uint32_t u;
    asm("cvt.rna.tf32.f32 %0, %1;" : "=r"(u) : "f"(f));
    return u;
}

__device__ __forceinline__ uint32_t pack_bf16(float lo, float hi) {
    __nv_bfloat162 h = __floats2bfloat162_rn(lo, hi);   // .x = lo (low 16 bits)
    return *reinterpret_cast<uint32_t*>(&h);
}

__device__ __forceinline__ float2 unpack_bf16(uint32_t u) {
    __nv_bfloat162 h = *reinterpret_cast<__nv_bfloat162*>(&u);
    return __bfloat1622float2(h);                        // .x = low half
}

__device__ __forceinline__ void mma_tf32(float c[4],
                                         uint32_t a0, uint32_t a1, uint32_t a2, uint32_t a3,
                                         uint32_t b0, uint32_t b1) {
    asm volatile(
        "mma.sync.aligned.m16n8k8.row.col.f32.tf32.tf32.f32 "
        "{%0,%1,%2,%3}, {%4,%5,%6,%7}, {%8,%9}, {%0,%1,%2,%3};\n"
        : "+f"(c[0]), "+f"(c[1]), "+f"(c[2]), "+f"(c[3])
        : "r"(a0), "r"(a1), "r"(a2), "r"(a3), "r"(b0), "r"(b1));
}

// ---------------- edge dtype probe (int64 vs int32) ----------------
__device__ __forceinline__ int edge_at(const void* ei, int idx) {
    int v;
    if (g_is64) v = (int)((const long long*)ei)[idx];
    else        v = ((const int*)ei)[idx];
    return min(max(v, 0), NN - 1);
}

// ---------------- CSR build ----------------
__global__ void k_zero(const void* ei) {
    int i = blockIdx.x * blockDim.x + threadIdx.x;
    if (i < NN) { g_cnt[i] = 0; g_fill[i] = 0; }
    if (i == 0) {   // dtype probe merged here
        const long long* p = (const long long*)ei;
        int ok = 1;
        #pragma unroll
        for (int j = 0; j < 4; j++) {
            long long v = p[j];
            if (v < 0 || v >= NN) ok = 0;
        }
        g_is64 = ok;
    }
}

__global__ void k_count(const void* __restrict__ ei) {
    int e = blockIdx.x * blockDim.x + threadIdx.x;
    if (e < EE) atomicAdd(&g_cnt[edge_at(ei, EE + e)], 1);
}

__global__ void k_scanA() {
    __shared__ int tmp[SB];
    int tid = threadIdx.x;
    int i = blockIdx.x * SB + tid;
    int v = (i < NN) ? g_cnt[i] : 0;
    tmp[tid] = v; __syncthreads();
    for (int off = 1; off < SB; off <<= 1) {
        int t = (tid >= off) ? tmp[tid - off] : 0;
        __syncthreads();
        if (tid >= off) tmp[tid] += t;
        __syncthreads();
    }
    if (i < NN) g_row[i + 1] = tmp[tid];
    if (tid == SB - 1) g_part[blockIdx.x] = tmp[tid];
}

__global__ void k_scanB() {
    __shared__ int tmp[SB];
    int tid = threadIdx.x;
    int v = (tid < NBLK) ? g_part[tid] : 0;
    tmp[tid] = v; __syncthreads();
    for (int off = 1; off < SB; off <<= 1) {
        int t = (tid >= off) ? tmp[tid - off] : 0;
        __syncthreads();
        if (tid >= off) tmp[tid] += t;
        __syncthreads();
    }
    if (tid < NBLK) g_part[tid] = tmp[tid] - v;   // exclusive block offsets
}

__global__ void k_scanC() {   // also computes g_dis (merged)
    int i = blockIdx.x * blockDim.x + threadIdx.x;
    if (i < NN) {
        g_row[i + 1] += g_part[i / SB];
        if (i == 0) g_row[0] = 0;
        g_dis[i] = rsqrtf((float)g_cnt[i] + 1.0f);
    }
}

__global__ void k_fill(const void* __restrict__ ei) {
    int e = blockIdx.x * blockDim.x + threadIdx.x;
    if (e < EE) {
        int d = edge_at(ei, EE + e);
        int s = edge_at(ei, e);
        int p = g_row[d] + atomicAdd(&g_fill[d], 1);
        g_col[p] = s;
        g_en[p] = g_dis[s] * g_dis[d];
    }
}

// ---------------- layer 1: aggregate x (2 feats) then [N,2]@[2,32]+b1, relu -> g_hB (bf16) ----------------
__global__ void k_layer1(const float* __restrict__ x,
                         const float* __restrict__ W1,
                         const float* __restrict__ b1) {
    __shared__ float w[64], bb[32];
    if (threadIdx.x < 64) w[threadIdx.x] = W1[threadIdx.x];
    if (threadIdx.x < 32) bb[threadIdx.x] = b1[threadIdx.x];
    __syncthreads();
    int v = blockIdx.x * blockDim.x + threadIdx.x;
    if (v >= NN) return;
    float dv = g_dis[v];
    float a0 = dv * dv * x[2 * v];
    float a1 = dv * dv * x[2 * v + 1];
    int e0 = g_row[v], e1 = g_row[v + 1];
    for (int e = e0; e < e1; e++) {
        int s = g_col[e];
        float nm = g_en[e];
        a0 += nm * x[2 * s];
        a1 += nm * x[2 * s + 1];
    }
    uint32_t* out = &g_hB[(size_t)v * 16];
    #pragma unroll
    for (int j = 0; j < 16; j++) {
        float r0 = fmaxf(a0 * w[2 * j]     + a1 * w[32 + 2 * j]     + bb[2 * j],     0.0f);
        float r1 = fmaxf(a0 * w[2 * j + 1] + a1 * w[32 + 2 * j + 1] + bb[2 * j + 1], 0.0f);
        out[j] = pack_bf16(r0, r1);
    }
}

// ---------------- aggregation, 128 feats (bf16 rows, 256B): warp per node, unroll-4 gathers ----------------
template <bool IN_A>
__global__ void __launch_bounds__(256) k_agg128() {
    const uint32_t* hin = IN_A ? g_hA : g_hB;
    int v = blockIdx.x * 8 + (threadIdx.x >> 5);   // 25000 blocks x 8 warps = NN exactly
    int lane = threadIdx.x & 31;

    float dv = g_dis[v];
    float sn = dv * dv;
    uint2 u = __ldg((const uint2*)(hin + (size_t)v * 64) + lane);
    float2 p0 = unpack_bf16(u.x), p1 = unpack_bf16(u.y);
    float a0 = sn * p0.x, a1 = sn * p0.y, a2 = sn * p1.x, a3 = sn * p1.y;

    int e  = g_row[v];
    int e1 = g_row[v + 1];
    for (; e + 3 < e1; e += 4) {
        int   s0 = g_col[e],   s1 = g_col[e+1], s2 = g_col[e+2], s3 = g_col[e+3];
        float m0 = g_en[e],    m1 = g_en[e+1],  m2 = g_en[e+2],  m3 = g_en[e+3];
        uint2 u0 = __ldg((const uint2*)(hin + (size_t)s0 * 64) + lane);
        uint2 u1 = __ldg((const uint2*)(hin + (size_t)s1 * 64) + lane);
        uint2 u2 = __ldg((const uint2*)(hin + (size_t)s2 * 64) + lane);
        uint2 u3 = __ldg((const uint2*)(hin + (size_t)s3 * 64) + lane);
        float2 q;
        q = unpack_bf16(u0.x); a0 += m0*q.x; a1 += m0*q.y;
        q = unpack_bf16(u0.y); a2 += m0*q.x; a3 += m0*q.y;
        q = unpack_bf16(u1.x); a0 += m1*q.x; a1 += m1*q.y;
        q = unpack_bf16(u1.y); a2 += m1*q.x; a3 += m1*q.y;
        q = unpack_bf16(u2.x); a0 += m2*q.x; a1 += m2*q.y;
        q = unpack_bf16(u2.y); a2 += m2*q.x; a3 += m2*q.y;
        q = unpack_bf16(u3.x); a0 += m3*q.x; a1 += m3*q.y;
        q = unpack_bf16(u3.y); a2 += m3*q.x; a3 += m3*q.y;
    }
    for (; e < e1; e++) {
        int   s0 = g_col[e];
        float m0 = g_en[e];
        uint2 u0 = __ldg((const uint2*)(hin + (size_t)s0 * 64) + lane);
        float2 q;
        q = unpack_bf16(u0.x); a0 += m0*q.x; a1 += m0*q.y;
        q = unpack_bf16(u0.y); a2 += m0*q.x; a3 += m0*q.y;
    }

    uint4 t;
    t.x = f2tf32(a0); t.y = f2tf32(a1); t.z = f2tf32(a2); t.w = f2tf32(a3);
    ((uint4*)(g_hC + (size_t)v * 128))[lane] = t;
}

// ---------------- aggregation, 32 feats (bf16, 64B rows): warp per node, lanes 0..15 active ----------------
__global__ void __launch_bounds__(256) k_agg32() {
    const uint32_t* hin = g_hB;
    int v = blockIdx.x * 8 + (threadIdx.x >> 5);
    int lane = threadIdx.x & 31;
    if (lane >= 16) return;

    float dv = g_dis[v];
    float sn = dv * dv;
    float2 p = unpack_bf16(__ldg(hin + (size_t)v * 16 + lane));
    float a0 = sn * p.x, a1 = sn * p.y;

    int e  = g_row[v];
    int e1 = g_row[v + 1];
    for (; e + 3 < e1; e += 4) {
        int   s0 = g_col[e],   s1 = g_col[e+1], s2 = g_col[e+2], s3 = g_col[e+3];
        float m0 = g_en[e],    m1 = g_en[e+1],  m2 = g_en[e+2],  m3 = g_en[e+3];
        float2 q0 = unpack_bf16(__ldg(hin + (size_t)s0 * 16 + lane));
        float2 q1 = unpack_bf16(__ldg(hin + (size_t)s1 * 16 + lane));
        float2 q2 = unpack_bf16(__ldg(hin + (size_t)s2 * 16 + lane));
        float2 q3 = unpack_bf16(__ldg(hin + (size_t)s3 * 16 + lane));
        a0 += m0*q0.x + m1*q1.x + m2*q2.x + m3*q3.x;
        a1 += m0*q0.y + m1*q1.y + m2*q2.y + m3*q3.y;
    }
    for (; e < e1; e++) {
        float2 q = unpack_bf16(__ldg(hin + (size_t)g_col[e] * 16 + lane));
        a0 += g_en[e] * q.x;
        a1 += g_en[e] * q.y;
    }

    g_hC[(size_t)v * 32 + 2 * lane]     = f2tf32(a0);
    g_hC[(size_t)v * 32 + 2 * lane + 1] = f2tf32(a1);
}

// ---------------- GEMM: [64,FIN] (tf32 bits in g_hC) @ [FIN,128] + b, relu -> bf16 h ----------------
// 256 threads, 3125 blocks. A tile staged through smem TRANSPOSED (As[k][72]):
//   - global loads: uint4, consecutive-row lane mapping (few sectors vs per-fragment LDG)
//   - As stride 72 -> store banks (8j+row) and fragment banks (8*tig+group) conflict-free
// W in smem stride 136 (bank 8k+n distinct -> conflict-free).
template <int FIN, bool OUT_A>
__global__ void __launch_bounds__(256) k_gemm(const float* __restrict__ W,
                                              const float* __restrict__ b) {
    constexpr int WS = 136;
    constexpr int AS = 72;
    extern __shared__ float smem[];
    float*    Ws = smem;                              // [FIN][WS], tf32 bits
    uint32_t* As = (uint32_t*)(smem + FIN * WS);      // [FIN][AS], tf32 bits, transposed (k-major)
    uint32_t* hout = OUT_A ? g_hA : g_hB;

    const int tid  = threadIdx.x;
    const int wid  = tid >> 5;
    const int lane = tid & 31;

    // load W into shared, converting to tf32
    for (int idx4 = tid; idx4 < FIN * 32; idx4 += 256) {
        int k  = idx4 >> 5;
        int n4 = idx4 & 31;
        float4 wv = ((const float4*)W)[idx4];
        uint4 t;
        t.x = f2tf32(wv.x); t.y = f2tf32(wv.y);
        t.z = f2tf32(wv.z); t.w = f2tf32(wv.w);
        *(uint4*)&Ws[k * WS + n4 * 4] = t;
    }

    // stage A tile (64 rows x FIN) into As transposed
    {
        const uint32_t* A = g_hC + (size_t)blockIdx.x * 64 * FIN;
        #pragma unroll
        for (int i = 0; i < FIN / 16; i++) {          // 64*FIN/4 uint4 / 256 threads
            int idx = tid + i * 256;
            int row = idx & 63;                        // consecutive rows per warp
            int c4  = idx >> 6;                        // uint4 column group
            uint4 v = __ldg((const uint4*)(A + (size_t)row * FIN) + c4);
            As[(4 * c4 + 0) * AS + row] = v.x;
            As[(4 * c4 + 1) * AS + row] = v.y;
            As[(4 * c4 + 2) * AS + row] = v.z;
            As[(4 * c4 + 3) * AS + row] = v.w;
        }
    }
    __syncthreads();

    const uint32_t* WsU = (const uint32_t*)Ws;

    const int rowt = wid & 1;          // 2 row tiles of 32
    const int colt = wid >> 1;         // 4 col tiles of 32
    const int r_base = rowt * 32;
    const int n_base = colt * 32;
    const int group = lane >> 2;       // 0..7
    const int tig   = lane & 3;        // 0..3

    float C[2][4][4];
    #pragma unroll
    for (int mi = 0; mi < 2; mi++)
        #pragma unroll
        for (int ni = 0; ni < 4; ni++)
            #pragma unroll
            for (int j = 0; j < 4; j++) C[mi][ni][j] = 0.0f;

    #pragma unroll
    for (int k0 = 0; k0 < FIN; k0 += 8) {
        uint32_t a[2][4];
        #pragma unroll
        for (int mi = 0; mi < 2; mi++) {
            int r0 = r_base + mi * 16 + group;
            a[mi][0] = As[(k0 + tig)     * AS + r0];
            a[mi][1] = As[(k0 + tig)     * AS + r0 + 8];
            a[mi][2] = As[(k0 + tig + 4) * AS + r0];
            a[mi][3] = As[(k0 + tig + 4) * AS + r0 + 8];
        }
        #pragma unroll
        for (int ni = 0; ni < 4; ni++) {
            int nc = n_base + ni * 8 + group;
            uint32_t b0 = WsU[(k0 + tig) * WS + nc];
            uint32_t b1 = WsU[(k0 + tig + 4) * WS + nc];
            mma_tf32(C[0][ni], a[0][0], a[0][1], a[0][2], a[0][3], b0, b1);
            mma_tf32(C[1][ni], a[1][0], a[1][1], a[1][2], a[1][3], b0, b1);
        }
    }

    // epilogue: bias + relu, pack to bf16x2 (cols 2tig, 2tig+1 are adjacent)
    #pragma unroll
    for (int ni = 0; ni < 4; ni++) {
        int col = n_base + ni * 8 + 2 * tig;
        float2 bb = __ldg((const float2*)&b[col]);
        #pragma unroll
        for (int mi = 0; mi < 2; mi++) {
            int row0 = blockIdx.x * 64 + r_base + mi * 16 + group;
            float o00 = fmaxf(C[mi][ni][0] + bb.x, 0.0f);
            float o01 = fmaxf(C[mi][ni][1] + bb.y, 0.0f);
            float o10 = fmaxf(C[mi][ni][2] + bb.x, 0.0f);
            float o11 = fmaxf(C[mi][ni][3] + bb.y, 0.0f);
            hout[(size_t)row0 * 64 + (col >> 1)]       = pack_bf16(o00, o01);
            hout[(size_t)(row0 + 8) * 64 + (col >> 1)] = pack_bf16(o10, o11);
        }
    }
}

// ---------------- final: out = leakyrelu(h5 @ Wl + bl), one warp per node ----------------
__global__ void k_final(const float* __restrict__ Wl,
                        const float* __restrict__ bl,
                        float* __restrict__ out) {
    int warp = (blockIdx.x * blockDim.x + threadIdx.x) >> 5;   // exactly NN warps
    int lane = threadIdx.x & 31;
    uint2 u = __ldg((const uint2*)(g_hB + (size_t)warp * 64) + lane);
    float2 p0 = unpack_bf16(u.x), p1 = unpack_bf16(u.y);
    float4 w  = __ldg((const float4*)&Wl[lane * 4]);
    float s = p0.x * w.x + p0.y * w.y + p1.x * w.z + p1.y * w.w;
    #pragma unroll
    for (int off = 16; off; off >>= 1) s += __shfl_down_sync(0xFFFFFFFFu, s, off);
    if (lane == 0) {
        s += __ldg(bl);
        out[warp] = (s > 0.0f) ? s : 0.01f * s;
    }
}

// ---------------- launch ----------------
extern "C" void kernel_launch(void* const* d_in, const int* in_sizes, int n_in,
                              void* d_out, int out_size) {
    int ix = 0, ie = 1, iW1 = 2, ib1 = 3, iW2 = 4, ib2 = 5, iW3 = 6, ib3 = 7,
        iW4 = 8, ib4 = 9, iW5 = 10, ib5 = 11, iWl = 12, ibl = 13;
    if (n_in >= 14 && in_sizes[0] != 2 * NN) {
        if (in_sizes[0] == 64 && in_sizes[1] == 4096) {
            iW1 = 0; iW2 = 1; iW3 = 2; iW4 = 3; iW5 = 4; iWl = 5;
            ib1 = 6; ib2 = 7; ib3 = 8; ib4 = 9; ib5 = 10; ibl = 11;
            ie = 12; ix = 13;
        }
    }

    const float* x  = (const float*)d_in[ix];
    const void*  ei = d_in[ie];
    const float* W1 = (const float*)d_in[iW1];
    const float* b1 = (const float*)d_in[ib1];
    const float* W2 = (const float*)d_in[iW2];
    const float* b2 = (const float*)d_in[ib2];
    const float* W3 = (const float*)d_in[iW3];
    const float* b3 = (const float*)d_in[ib3];
    const float* W4 = (const float*)d_in[iW4];
    const float* b4 = (const float*)d_in[ib4];
    const float* W5 = (const float*)d_in[iW5];
    const float* b5 = (const float*)d_in[ib5];
    const float* Wl = (const float*)d_in[iWl];
    const float* bl = (const float*)d_in[ibl];
    float* out = (float*)d_out;

    const int sh32  = (32  * 136 + 32  * 72) * 4;   // 26,624 B
    const int sh128 = (128 * 136 + 128 * 72) * 4;   // 106,496 B
    cudaFuncSetAttribute(k_gemm<32,  true >, cudaFuncAttributeMaxDynamicSharedMemorySize, sh32);
    cudaFuncSetAttribute(k_gemm<128, true >, cudaFuncAttributeMaxDynamicSharedMemorySize, sh128);
    cudaFuncSetAttribute(k_gemm<128, false>, cudaFuncAttributeMaxDynamicSharedMemorySize, sh128);

    // CSR + norms (dtype probe merged into k_zero)
    k_zero <<<(NN + 255) / 256, 256>>>(ei);
    k_count<<<(EE + 255) / 256, 256>>>(ei);
    k_scanA<<<NBLK, SB>>>();
    k_scanB<<<1, SB>>>();
    k_scanC<<<(NN + 255) / 256, 256>>>();   // + g_dis
    k_fill <<<(EE + 255) / 256, 256>>>(ei);

    // layers: agg (bf16 gathers, fp32 accum, tf32 out) then tf32 MMA gemm (bf16 out)
    k_layer1<<<(NN + 255) / 256, 256>>>(x, W1, b1);            // x -> hB [N,32] bf16
    k_agg32 <<<NN / 8, 256>>>();                               // hB -> C [N,32] tf32
    k_gemm<32,  true ><<<3125, 256, sh32 >>>(W2, b2);          // C -> hA [N,128] bf16
    k_agg128<true ><<<NN / 8, 256>>>();                        // hA -> C
    k_gemm<128, false><<<3125, 256, sh128>>>(W3, b3);          // C -> hB
    k_agg128<false><<<NN / 8, 256>>>();                        // hB -> C
    k_gemm<128, true ><<<3125, 256, sh128>>>(W4, b4);          // C -> hA
    k_agg128<true ><<<NN / 8, 256>>>();                        // hA -> C
    k_gemm<128, false><<<3125, 256, sh128>>>(W5, b5);          // C -> hB

    k_final<<<NN / 8, 256>>>(Wl, bl, out);                     // 8 warps/block, exact
}